// round 3
// baseline (speedup 1.0000x reference)
#include <cuda_runtime.h>
#include <cuda_bf16.h>
#include <cstdint>

typedef unsigned long long ull;

// Problem constants
#define BB   4096
#define TT   512
#define INF  3
#define HH   128
#define G4   512   // 4*H

// Persistent-kernel geometry
#define ROWS 32          // batch rows per CTA
#define CTAS (BB/ROWS)   // 128
#define THR  256

// ---------------- device scratch (no cudaMalloc allowed) ----------------
__device__ __align__(16) float g_Wt[HH * G4];  // W_hh transposed: [k][j]  (k-major, 1MB)
__device__ __align__(16) float g_b[G4];        // b_ih + b_hh
__device__ __align__(16) float g_h[BB * HH];   // final hidden state
__device__ float g_scale[HH];
__device__ float g_shift[HH];

// ---------------- f32x2 packed primitives (sm_100 FFMA2 path) ----------------
__device__ __forceinline__ ull f2add(ull a, ull b) {
    ull d; asm("add.rn.f32x2 %0,%1,%2;" : "=l"(d) : "l"(a), "l"(b)); return d;
}
__device__ __forceinline__ ull f2mul(ull a, ull b) {
    ull d; asm("mul.rn.f32x2 %0,%1,%2;" : "=l"(d) : "l"(a), "l"(b)); return d;
}
__device__ __forceinline__ ull f2fma(ull a, ull b, ull c) {
    ull d; asm("fma.rn.f32x2 %0,%1,%2,%3;" : "=l"(d) : "l"(a), "l"(b), "l"(c)); return d;
}
__device__ __forceinline__ ull dup2(float v) {
    ull r; asm("mov.b64 %0,{%1,%1};" : "=l"(r) : "f"(v)); return r;
}
__device__ __forceinline__ float2 unpk(ull a) {
    float2 f; asm("mov.b64 {%0,%1},%2;" : "=f"(f.x), "=f"(f.y) : "l"(a)); return f;
}
__device__ __forceinline__ ull pk(float x, float y) {
    ull r; asm("mov.b64 %0,{%1,%2};" : "=l"(r) : "f"(x), "f"(y)); return r;
}

// ---------------- packed MUFU-free transcendentals ----------------
// 2^t (both lanes), t must be in [-32, 32]
__device__ __forceinline__ ull exp2_2(ull t) {
    ull z  = f2add(t, dup2(12582912.0f));          // round-to-int magic
    ull nf = f2add(z, dup2(-12582912.0f));
    ull f  = f2fma(nf, dup2(-1.0f), t);            // frac in [-0.5,0.5]
    ull p  = f2fma(f, dup2(0.00133335581f), dup2(0.00961812911f));
    p = f2fma(p, f, dup2(0.05550410866f));
    p = f2fma(p, f, dup2(0.24022650700f));
    p = f2fma(p, f, dup2(0.69314718056f));
    p = f2fma(p, f, dup2(1.0f));
    float2 zf = unpk(z), pf = unpk(p);
    float rx = __int_as_float(__float_as_int(pf.x) + ((__float_as_int(zf.x) - 0x4B400000) << 23));
    float ry = __int_as_float(__float_as_int(pf.y) + ((__float_as_int(zf.y) - 0x4B400000) << 23));
    return pk(rx, ry);
}

// 1/d (both lanes), d > 0 normal range. Bit-hack seed + 3 Newton.
__device__ __forceinline__ ull rcp2(ull d) {
    float2 df = unpk(d);
    float sx = __int_as_float(0x7EF477D5 - __float_as_int(df.x));
    float sy = __int_as_float(0x7EF477D5 - __float_as_int(df.y));
    ull y  = pk(sx, sy);
    ull nd = f2mul(d, dup2(-1.0f));
    y = f2mul(y, f2fma(nd, y, dup2(2.0f)));
    y = f2mul(y, f2fma(nd, y, dup2(2.0f)));
    y = f2mul(y, f2fma(nd, y, dup2(2.0f)));
    return y;
}

__device__ __forceinline__ ull clamp2(ull a, float lo, float hi) {
    float2 f = unpk(a);
    f.x = fminf(fmaxf(f.x, lo), hi);
    f.y = fminf(fmaxf(f.y, lo), hi);
    return pk(f.x, f.y);
}

__device__ __forceinline__ ull sigmoid2(ull x) {
    ull t = clamp2(f2mul(x, dup2(-1.44269504089f)), -30.0f, 30.0f);
    return rcp2(f2add(exp2_2(t), dup2(1.0f)));
}
__device__ __forceinline__ ull tanh2(ull x) {
    ull t = clamp2(f2mul(x, dup2(2.88539008178f)), -30.0f, 30.0f);
    ull r = rcp2(f2add(exp2_2(t), dup2(1.0f)));
    return f2fma(r, dup2(-2.0f), dup2(1.0f));
}

// scalar versions for the tiny epilogue
__device__ __forceinline__ float fast_exp2s(float t) {
    float z  = __fadd_rn(t, 12582912.0f);
    int   ni = __float_as_int(z);
    float nf = __fsub_rn(z, 12582912.0f);
    float f  = t - nf;
    float p  = 0.00133335581f;
    p = __fmaf_rn(p, f, 0.00961812911f);
    p = __fmaf_rn(p, f, 0.05550410866f);
    p = __fmaf_rn(p, f, 0.24022650700f);
    p = __fmaf_rn(p, f, 0.69314718056f);
    p = __fmaf_rn(p, f, 1.0f);
    return __int_as_float(__float_as_int(p) + ((ni - 0x4B400000) << 23));
}
__device__ __forceinline__ float fsigmoid(float xv) {
    float t = fminf(fmaxf(-1.44269504089f * xv, -30.0f), 30.0f);
    float d = 1.0f + fast_exp2s(t);
    float y = __int_as_float(0x7EF477D5 - __float_as_int(d));
    y = y * __fmaf_rn(-d, y, 2.0f);
    y = y * __fmaf_rn(-d, y, 2.0f);
    y = y * __fmaf_rn(-d, y, 2.0f);
    return y;
}

// ---------------- prep: transpose W_hh, fuse biases ----------------
__global__ void prep_kernel(const float* __restrict__ Whh,
                            const float* __restrict__ bih,
                            const float* __restrict__ bhh) {
    int idx = blockIdx.x * blockDim.x + threadIdx.x;
    if (idx < HH * G4) {
        int k = idx >> 9;
        int j = idx & 511;
        g_Wt[idx] = Whh[j * HH + k];
    }
    if (idx < G4) g_b[idx] = bih[idx] + bhh[idx];
}

// ---------------- persistent LSTM kernel (f32x2 packed) ----------------
// CTA: 32 batch rows.  Thread (ty, hx): ty -> 8 rows, hx -> hidden col pair (2hx, 2hx+1).
__global__ void __launch_bounds__(THR, 1) lstm_main(
    const float* __restrict__ x, const float* __restrict__ Wih)
{
    __shared__ ull  hs2[ROWS][HH];   // h duplicated pairs {h,h}  (32 KB)
    __shared__ ull  ws2[INF][4][64]; // packed W_ih pairs          (6 KB)
    __shared__ float xs[ROWS][INF];

    const int tid = threadIdx.x;
    const int hx  = tid & 63;
    const int ty  = tid >> 6;
    const int hc0 = hx * 2;
    const int r0  = ty * 8;
    const int b0  = blockIdx.x * ROWS;

    // zero h (duplicated form)
    for (int i = tid; i < ROWS * HH; i += THR) ((ull*)hs2)[i] = 0ULL;

    // pack W_ih pairs into smem: ws2[kx][g][hx] = {Wih[(g*128+2hx)*3+kx], Wih[(g*128+2hx+1)*3+kx]}
    for (int i = tid; i < INF * 4 * 64; i += THR) {
        int hxx = i & 63, gg = (i >> 6) & 3, kx = i >> 8;
        int j0 = gg * HH + hxx * 2;
        ws2[kx][gg][hxx] = pk(Wih[j0 * INF + kx], Wih[(j0 + 1) * INF + kx]);
    }

    // packed bias pairs
    ull bias2[4];
#pragma unroll
    for (int g = 0; g < 4; ++g)
        bias2[g] = *(const ull*)&g_b[g * HH + hc0];

    const int xr = tid / 3;
    const int xk = tid - xr * 3;
    if (tid < 96) xs[xr][xk] = x[(b0 + xr) * (TT * INF) + xk];  // t = 0
    __syncthreads();

    const ull* __restrict__ Wp = (const ull*)g_Wt;

    ull cst2[8];
#pragma unroll
    for (int r = 0; r < 8; ++r) cst2[r] = 0ULL;

    for (int t = 0; t < TT; ++t) {
        ull z2[4][8];
#pragma unroll
        for (int g = 0; g < 4; ++g)
#pragma unroll
            for (int r = 0; r < 8; ++r) z2[g][r] = bias2[g];

        // x contribution
#pragma unroll
        for (int kx = 0; kx < INF; ++kx) {
            ull wx[4];
#pragma unroll
            for (int g = 0; g < 4; ++g) wx[g] = ws2[kx][g][hx];
#pragma unroll
            for (int r = 0; r < 8; ++r) {
                ull xd = dup2(xs[r0 + r][kx]);
#pragma unroll
                for (int g = 0; g < 4; ++g) z2[g][r] = f2fma(xd, wx[g], z2[g][r]);
            }
        }

        // h @ W_hh^T  — packed: 2 hidden cols per FMA2
#pragma unroll 2
        for (int k = 0; k < HH; k += 2) {
            ull w0[4], w1[4];
#pragma unroll
            for (int g = 0; g < 4; ++g) {
                w0[g] = Wp[k * 256 + g * 64 + hx];
                w1[g] = Wp[(k + 1) * 256 + g * 64 + hx];
            }
#pragma unroll
            for (int r = 0; r < 8; ++r) {
                ulonglong2 hv = *(const ulonglong2*)&hs2[r0 + r][k];  // {hk,hk},{hk1,hk1}
#pragma unroll
                for (int g = 0; g < 4; ++g) z2[g][r] = f2fma(hv.x, w0[g], z2[g][r]);
#pragma unroll
                for (int g = 0; g < 4; ++g) z2[g][r] = f2fma(hv.y, w1[g], z2[g][r]);
            }
        }

        // nonlinearities + cell update, fully packed
        ull hn2[8];
#pragma unroll
        for (int r = 0; r < 8; ++r) {
            ull i_ = sigmoid2(z2[0][r]);
            ull f_ = sigmoid2(z2[1][r]);
            ull g_ = tanh2   (z2[2][r]);
            ull o_ = sigmoid2(z2[3][r]);
            ull cn = f2fma(f_, cst2[r], f2mul(i_, g_));
            cst2[r] = cn;
            hn2[r]  = f2mul(o_, tanh2(cn));
        }

        __syncthreads();   // all reads of hs2 / xs done
#pragma unroll
        for (int r = 0; r < 8; ++r) {
            float2 h = unpk(hn2[r]);
            ulonglong2 st;
            st.x = dup2(h.x);
            st.y = dup2(h.y);
            *(ulonglong2*)&hs2[r0 + r][hc0] = st;
        }
        if (tid < 96 && t + 1 < TT)
            xs[xr][xk] = x[(b0 + xr) * (TT * INF) + (t + 1) * INF + xk];
        __syncthreads();
    }

    // final h -> global (take .x of each duplicated pair)
    for (int i = tid; i < ROWS * HH; i += THR) {
        float2 hvv = unpk(((ull*)hs2)[i]);
        g_h[b0 * HH + i] = hvv.x;
    }
}

// ---------------- BN stats (two-pass, per feature) ----------------
__global__ void bn_stats(const float* __restrict__ gamma,
                         const float* __restrict__ beta) {
    const int j = blockIdx.x;
    const int tid = threadIdx.x;
    __shared__ float red[256];
    __shared__ float mean_s;

    float s = 0.0f;
    for (int r = tid; r < BB; r += 256) s += g_h[r * HH + j];
    red[tid] = s; __syncthreads();
    for (int o = 128; o > 0; o >>= 1) { if (tid < o) red[tid] += red[tid + o]; __syncthreads(); }
    if (tid == 0) mean_s = red[0] * (1.0f / BB);
    __syncthreads();
    const float m = mean_s;

    float s2 = 0.0f;
    for (int r = tid; r < BB; r += 256) { float d = g_h[r * HH + j] - m; s2 += d * d; }
    red[tid] = s2; __syncthreads();
    for (int o = 128; o > 0; o >>= 1) { if (tid < o) red[tid] += red[tid + o]; __syncthreads(); }
    if (tid == 0) {
        float var  = red[0] * (1.0f / BB);
        float rstd = rsqrtf(var + 1e-5f);
        g_scale[j] = rstd * gamma[j];
        g_shift[j] = beta[j] - m * rstd * gamma[j];
    }
}

// ---------------- BN apply + LeakyReLU + FC + sigmoid ----------------
__global__ void out_kernel(const float* __restrict__ fcw,
                           const float* __restrict__ fcb,
                           float* __restrict__ out) {
    const int lane = threadIdx.x & 31;
    const int warp = threadIdx.x >> 5;
    const int b = blockIdx.x * 4 + warp;
    float acc = 0.0f;
#pragma unroll
    for (int q = 0; q < 4; ++q) {
        int j = lane + q * 32;
        float v = __fmaf_rn(g_h[b * HH + j], g_scale[j], g_shift[j]);
        v = (v >= 0.0f) ? v : 0.01f * v;
        acc = __fmaf_rn(v, fcw[j], acc);
    }
#pragma unroll
    for (int o = 16; o > 0; o >>= 1) acc += __shfl_xor_sync(0xffffffffu, acc, o);
    if (lane == 0) out[b] = fsigmoid(acc + fcb[0]);
}

// ---------------- launch ----------------
extern "C" void kernel_launch(void* const* d_in, const int* in_sizes, int n_in,
                              void* d_out, int out_size) {
    const float* x     = (const float*)d_in[0];
    const float* W_ih  = (const float*)d_in[1];
    const float* W_hh  = (const float*)d_in[2];
    const float* b_ih  = (const float*)d_in[3];
    const float* b_hh  = (const float*)d_in[4];
    const float* gamma = (const float*)d_in[5];
    const float* beta  = (const float*)d_in[6];
    const float* fc_w  = (const float*)d_in[7];
    const float* fc_b  = (const float*)d_in[8];
    float* out = (float*)d_out;

    prep_kernel<<<(HH * G4 + 255) / 256, 256>>>(W_hh, b_ih, b_hh);
    lstm_main<<<CTAS, THR>>>(x, W_ih);
    bn_stats<<<HH, 256>>>(gamma, beta);
    out_kernel<<<BB / 4, 128>>>(fc_w, fc_b, out);
}

// round 4
// speedup vs baseline: 1.0011x; 1.0011x over previous
#include <cuda_runtime.h>
#include <cuda_bf16.h>
#include <cstdint>

typedef unsigned long long ull;

// Problem constants
#define BB   4096
#define TT   512
#define INF  3
#define HH   128
#define G4   512   // 4*H

// Persistent-kernel geometry
#define ROWS 32          // batch rows per CTA
#define CTAS (BB/ROWS)   // 128
#define THR  256

// ---------------- device scratch (no cudaMalloc allowed) ----------------
__device__ __align__(16) float g_Wt[HH * G4];  // W_hh transposed: [k][j]  (k-major, 1MB)
__device__ __align__(16) float g_b[G4];        // b_ih + b_hh
__device__ __align__(16) float g_h[BB * HH];   // final hidden state
__device__ float g_scale[HH];
__device__ float g_shift[HH];

// ---------------- f32x2 packed primitives (sm_100 FFMA2 path) ----------------
__device__ __forceinline__ ull f2add(ull a, ull b) {
    ull d; asm("add.rn.f32x2 %0,%1,%2;" : "=l"(d) : "l"(a), "l"(b)); return d;
}
__device__ __forceinline__ ull f2mul(ull a, ull b) {
    ull d; asm("mul.rn.f32x2 %0,%1,%2;" : "=l"(d) : "l"(a), "l"(b)); return d;
}
__device__ __forceinline__ ull f2fma(ull a, ull b, ull c) {
    ull d; asm("fma.rn.f32x2 %0,%1,%2,%3;" : "=l"(d) : "l"(a), "l"(b), "l"(c)); return d;
}
__device__ __forceinline__ ull dup2(float v) {
    ull r; asm("mov.b64 %0,{%1,%1};" : "=l"(r) : "f"(v)); return r;
}
__device__ __forceinline__ float2 unpk(ull a) {
    float2 f; asm("mov.b64 {%0,%1},%2;" : "=f"(f.x), "=f"(f.y) : "l"(a)); return f;
}
__device__ __forceinline__ ull pk(float x, float y) {
    ull r; asm("mov.b64 %0,{%1,%2};" : "=l"(r) : "f"(x), "f"(y)); return r;
}

// ---------------- packed MUFU-free transcendentals ----------------
// 2^t (both lanes), t must be in [-32, 32]
__device__ __forceinline__ ull exp2_2(ull t) {
    ull z  = f2add(t, dup2(12582912.0f));          // round-to-int magic
    ull nf = f2add(z, dup2(-12582912.0f));
    ull f  = f2fma(nf, dup2(-1.0f), t);            // frac in [-0.5,0.5]
    ull p  = f2fma(f, dup2(0.00133335581f), dup2(0.00961812911f));
    p = f2fma(p, f, dup2(0.05550410866f));
    p = f2fma(p, f, dup2(0.24022650700f));
    p = f2fma(p, f, dup2(0.69314718056f));
    p = f2fma(p, f, dup2(1.0f));
    float2 zf = unpk(z), pf = unpk(p);
    float rx = __int_as_float(__float_as_int(pf.x) + ((__float_as_int(zf.x) - 0x4B400000) << 23));
    float ry = __int_as_float(__float_as_int(pf.y) + ((__float_as_int(zf.y) - 0x4B400000) << 23));
    return pk(rx, ry);
}

// 1/d (both lanes), d > 0 normal range. Bit-hack seed + 3 Newton.
__device__ __forceinline__ ull rcp2(ull d) {
    float2 df = unpk(d);
    float sx = __int_as_float(0x7EF477D5 - __float_as_int(df.x));
    float sy = __int_as_float(0x7EF477D5 - __float_as_int(df.y));
    ull y  = pk(sx, sy);
    ull nd = f2mul(d, dup2(-1.0f));
    y = f2mul(y, f2fma(nd, y, dup2(2.0f)));
    y = f2mul(y, f2fma(nd, y, dup2(2.0f)));
    y = f2mul(y, f2fma(nd, y, dup2(2.0f)));
    return y;
}

__device__ __forceinline__ ull clamp2(ull a, float lo, float hi) {
    float2 f = unpk(a);
    f.x = fminf(fmaxf(f.x, lo), hi);
    f.y = fminf(fmaxf(f.y, lo), hi);
    return pk(f.x, f.y);
}

__device__ __forceinline__ ull sigmoid2(ull x) {
    ull t = clamp2(f2mul(x, dup2(-1.44269504089f)), -30.0f, 30.0f);
    return rcp2(f2add(exp2_2(t), dup2(1.0f)));
}
__device__ __forceinline__ ull tanh2(ull x) {
    ull t = clamp2(f2mul(x, dup2(2.88539008178f)), -30.0f, 30.0f);
    ull r = rcp2(f2add(exp2_2(t), dup2(1.0f)));
    return f2fma(r, dup2(-2.0f), dup2(1.0f));
}

// scalar versions for the tiny epilogue
__device__ __forceinline__ float fast_exp2s(float t) {
    float z  = __fadd_rn(t, 12582912.0f);
    int   ni = __float_as_int(z);
    float nf = __fsub_rn(z, 12582912.0f);
    float f  = t - nf;
    float p  = 0.00133335581f;
    p = __fmaf_rn(p, f, 0.00961812911f);
    p = __fmaf_rn(p, f, 0.05550410866f);
    p = __fmaf_rn(p, f, 0.24022650700f);
    p = __fmaf_rn(p, f, 0.69314718056f);
    p = __fmaf_rn(p, f, 1.0f);
    return __int_as_float(__float_as_int(p) + ((ni - 0x4B400000) << 23));
}
__device__ __forceinline__ float fsigmoid(float xv) {
    float t = fminf(fmaxf(-1.44269504089f * xv, -30.0f), 30.0f);
    float d = 1.0f + fast_exp2s(t);
    float y = __int_as_float(0x7EF477D5 - __float_as_int(d));
    y = y * __fmaf_rn(-d, y, 2.0f);
    y = y * __fmaf_rn(-d, y, 2.0f);
    y = y * __fmaf_rn(-d, y, 2.0f);
    return y;
}

// ---------------- prep: transpose W_hh, fuse biases ----------------
__global__ void prep_kernel(const float* __restrict__ Whh,
                            const float* __restrict__ bih,
                            const float* __restrict__ bhh) {
    int idx = blockIdx.x * blockDim.x + threadIdx.x;
    if (idx < HH * G4) {
        int k = idx >> 9;
        int j = idx & 511;
        g_Wt[idx] = Whh[j * HH + k];
    }
    if (idx < G4) g_b[idx] = bih[idx] + bhh[idx];
}

// ---------------- persistent LSTM kernel (f32x2 packed) ----------------
// CTA: 32 batch rows.  Thread (ty, hx): ty -> 8 rows, hx -> hidden col pair (2hx, 2hx+1).
__global__ void __launch_bounds__(THR, 1) lstm_main(
    const float* __restrict__ x, const float* __restrict__ Wih)
{
    __shared__ ull  hs2[ROWS][HH];   // h duplicated pairs {h,h}  (32 KB)
    __shared__ ull  ws2[INF][4][64]; // packed W_ih pairs          (6 KB)
    __shared__ float xs[ROWS][INF];

    const int tid = threadIdx.x;
    const int hx  = tid & 63;
    const int ty  = tid >> 6;
    const int hc0 = hx * 2;
    const int r0  = ty * 8;
    const int b0  = blockIdx.x * ROWS;

    // zero h (duplicated form)
    for (int i = tid; i < ROWS * HH; i += THR) ((ull*)hs2)[i] = 0ULL;

    // pack W_ih pairs into smem: ws2[kx][g][hx] = {Wih[(g*128+2hx)*3+kx], Wih[(g*128+2hx+1)*3+kx]}
    for (int i = tid; i < INF * 4 * 64; i += THR) {
        int hxx = i & 63, gg = (i >> 6) & 3, kx = i >> 8;
        int j0 = gg * HH + hxx * 2;
        ws2[kx][gg][hxx] = pk(Wih[j0 * INF + kx], Wih[(j0 + 1) * INF + kx]);
    }

    // packed bias pairs
    ull bias2[4];
#pragma unroll
    for (int g = 0; g < 4; ++g)
        bias2[g] = *(const ull*)&g_b[g * HH + hc0];

    const int xr = tid / 3;
    const int xk = tid - xr * 3;
    if (tid < 96) xs[xr][xk] = x[(b0 + xr) * (TT * INF) + xk];  // t = 0
    __syncthreads();

    const ull* __restrict__ Wp = (const ull*)g_Wt;

    ull cst2[8];
#pragma unroll
    for (int r = 0; r < 8; ++r) cst2[r] = 0ULL;

    for (int t = 0; t < TT; ++t) {
        ull z2[4][8];
#pragma unroll
        for (int g = 0; g < 4; ++g)
#pragma unroll
            for (int r = 0; r < 8; ++r) z2[g][r] = bias2[g];

        // x contribution
#pragma unroll
        for (int kx = 0; kx < INF; ++kx) {
            ull wx[4];
#pragma unroll
            for (int g = 0; g < 4; ++g) wx[g] = ws2[kx][g][hx];
#pragma unroll
            for (int r = 0; r < 8; ++r) {
                ull xd = dup2(xs[r0 + r][kx]);
#pragma unroll
                for (int g = 0; g < 4; ++g) z2[g][r] = f2fma(xd, wx[g], z2[g][r]);
            }
        }

        // h @ W_hh^T  — packed: 2 hidden cols per FMA2
#pragma unroll 2
        for (int k = 0; k < HH; k += 2) {
            ull w0[4], w1[4];
#pragma unroll
            for (int g = 0; g < 4; ++g) {
                w0[g] = Wp[k * 256 + g * 64 + hx];
                w1[g] = Wp[(k + 1) * 256 + g * 64 + hx];
            }
#pragma unroll
            for (int r = 0; r < 8; ++r) {
                ulonglong2 hv = *(const ulonglong2*)&hs2[r0 + r][k];  // {hk,hk},{hk1,hk1}
#pragma unroll
                for (int g = 0; g < 4; ++g) z2[g][r] = f2fma(hv.x, w0[g], z2[g][r]);
#pragma unroll
                for (int g = 0; g < 4; ++g) z2[g][r] = f2fma(hv.y, w1[g], z2[g][r]);
            }
        }

        // nonlinearities + cell update, fully packed
        ull hn2[8];
#pragma unroll
        for (int r = 0; r < 8; ++r) {
            ull i_ = sigmoid2(z2[0][r]);
            ull f_ = sigmoid2(z2[1][r]);
            ull g_ = tanh2   (z2[2][r]);
            ull o_ = sigmoid2(z2[3][r]);
            ull cn = f2fma(f_, cst2[r], f2mul(i_, g_));
            cst2[r] = cn;
            hn2[r]  = f2mul(o_, tanh2(cn));
        }

        __syncthreads();   // all reads of hs2 / xs done
#pragma unroll
        for (int r = 0; r < 8; ++r) {
            float2 h = unpk(hn2[r]);
            ulonglong2 st;
            st.x = dup2(h.x);
            st.y = dup2(h.y);
            *(ulonglong2*)&hs2[r0 + r][hc0] = st;
        }
        if (tid < 96 && t + 1 < TT)
            xs[xr][xk] = x[(b0 + xr) * (TT * INF) + (t + 1) * INF + xk];
        __syncthreads();
    }

    // final h -> global (take .x of each duplicated pair)
    for (int i = tid; i < ROWS * HH; i += THR) {
        float2 hvv = unpk(((ull*)hs2)[i]);
        g_h[b0 * HH + i] = hvv.x;
    }
}

// ---------------- BN stats (two-pass, per feature) ----------------
__global__ void bn_stats(const float* __restrict__ gamma,
                         const float* __restrict__ beta) {
    const int j = blockIdx.x;
    const int tid = threadIdx.x;
    __shared__ float red[256];
    __shared__ float mean_s;

    float s = 0.0f;
    for (int r = tid; r < BB; r += 256) s += g_h[r * HH + j];
    red[tid] = s; __syncthreads();
    for (int o = 128; o > 0; o >>= 1) { if (tid < o) red[tid] += red[tid + o]; __syncthreads(); }
    if (tid == 0) mean_s = red[0] * (1.0f / BB);
    __syncthreads();
    const float m = mean_s;

    float s2 = 0.0f;
    for (int r = tid; r < BB; r += 256) { float d = g_h[r * HH + j] - m; s2 += d * d; }
    red[tid] = s2; __syncthreads();
    for (int o = 128; o > 0; o >>= 1) { if (tid < o) red[tid] += red[tid + o]; __syncthreads(); }
    if (tid == 0) {
        float var  = red[0] * (1.0f / BB);
        float rstd = rsqrtf(var + 1e-5f);
        g_scale[j] = rstd * gamma[j];
        g_shift[j] = beta[j] - m * rstd * gamma[j];
    }
}

// ---------------- BN apply + LeakyReLU + FC + sigmoid ----------------
__global__ void out_kernel(const float* __restrict__ fcw,
                           const float* __restrict__ fcb,
                           float* __restrict__ out) {
    const int lane = threadIdx.x & 31;
    const int warp = threadIdx.x >> 5;
    const int b = blockIdx.x * 4 + warp;
    float acc = 0.0f;
#pragma unroll
    for (int q = 0; q < 4; ++q) {
        int j = lane + q * 32;
        float v = __fmaf_rn(g_h[b * HH + j], g_scale[j], g_shift[j]);
        v = (v >= 0.0f) ? v : 0.01f * v;
        acc = __fmaf_rn(v, fcw[j], acc);
    }
#pragma unroll
    for (int o = 16; o > 0; o >>= 1) acc += __shfl_xor_sync(0xffffffffu, acc, o);
    if (lane == 0) out[b] = fsigmoid(acc + fcb[0]);
}

// ---------------- launch ----------------
extern "C" void kernel_launch(void* const* d_in, const int* in_sizes, int n_in,
                              void* d_out, int out_size) {
    const float* x     = (const float*)d_in[0];
    const float* W_ih  = (const float*)d_in[1];
    const float* W_hh  = (const float*)d_in[2];
    const float* b_ih  = (const float*)d_in[3];
    const float* b_hh  = (const float*)d_in[4];
    const float* gamma = (const float*)d_in[5];
    const float* beta  = (const float*)d_in[6];
    const float* fc_w  = (const float*)d_in[7];
    const float* fc_b  = (const float*)d_in[8];
    float* out = (float*)d_out;

    prep_kernel<<<(HH * G4 + 255) / 256, 256>>>(W_hh, b_ih, b_hh);
    lstm_main<<<CTAS, THR>>>(x, W_ih);
    bn_stats<<<HH, 256>>>(gamma, beta);
    out_kernel<<<BB / 4, 128>>>(fc_w, fc_b, out);
}